// round 16
// baseline (speedup 1.0000x reference)
#include <cuda_runtime.h>
#include <cstdint>

#define DI static __device__ __forceinline__

// ---------------------------------------------------------------- constants
constexpr int B_ = 32, L_ = 720, V_ = 1024, P_ = 720, E_ = 8;
constexpr int NTOK = B_ * V_;                 // 32768 tokens
constexpr int OUT_MAIN = B_ * P_ * V_;        // 23592960
constexpr int MT = 128;                       // block M (tokens)
constexpr int NTILE = 128;                    // block N (output cols)
constexpr int NNT = 6;                        // ceil(720/128)
constexpr int BK = 32;                        // K per stage
constexpr int KSTEPS = 23;                    // 22 full + 1 half (zfill)
constexpr int NSTAGE = 3;

// smem geometry for the GEMM kernel
constexpr int SA = 36;                        // padded row stride (floats)
constexpr int STAGE_FLOATS = (MT + NTILE) * SA;      // 9216 floats
constexpr int STAGE_BYTES = STAGE_FLOATS * 4;        // 36864
constexpr int SM_TOK = 0;                     // 128 ints
constexpr int SM_W   = 512;                   // 128 floats
constexpr int SM_ST  = 1024;                  // stage buffers
constexpr int SM_TOTAL = SM_ST + NSTAGE * STAGE_BYTES;   // 111616

// ------------------------------------------------------- scratch (globals)
__device__ float g_Xt[(size_t)NTOK * L_];     // token-major input, tf32-rounded
__device__ float g_Wr[(size_t)E_ * P_ * L_];  // We tf32-rounded (16.6 MB)
__device__ float g_Ys0[(size_t)NTOK * P_];    // slot-0 contribution (94 MB)
__device__ float g_Ys1[(size_t)NTOK * P_];    // slot-1 contribution (94 MB)
__device__ float g_prob[(size_t)NTOK * E_];   // softmax probs
__device__ int   g_cnt[16];                   // per (slot,expert) counts
__device__ int   g_list [16 * NTOK];          // gathered token ids
__device__ float g_wlist[16 * NTOK];          // gate weights

// ------------------------------------------------------------- PTX helpers
DI uint32_t smem_u32(const void* p) {
    uint32_t a;
    asm("{ .reg .u64 t; cvta.to.shared.u64 t, %1; cvt.u32.u64 %0, t; }"
        : "=r"(a) : "l"(p));
    return a;
}

DI void cp16(uint32_t dst, const void* src, int srcbytes) {
    asm volatile("cp.async.cg.shared.global [%0], [%1], 16, %2;"
                 :: "r"(dst), "l"(src), "r"(srcbytes));
}
DI void cp_commit() { asm volatile("cp.async.commit_group;" ::: "memory"); }
template <int N>
DI void cp_wait() { asm volatile("cp.async.wait_group %0;" :: "n"(N) : "memory"); }

DI float f2tf(float f) {
    uint32_t r;
    asm("cvt.rna.tf32.f32 %0, %1;" : "=r"(r) : "f"(f));
    return __uint_as_float(r);
}

DI void mma_tf32(float* d, const uint32_t* a, const uint32_t* b) {
    asm volatile(
        "mma.sync.aligned.m16n8k8.row.col.f32.tf32.tf32.f32 "
        "{%0,%1,%2,%3}, {%4,%5,%6,%7}, {%8,%9}, {%0,%1,%2,%3};"
        : "+f"(d[0]), "+f"(d[1]), "+f"(d[2]), "+f"(d[3])
        : "r"(a[0]), "r"(a[1]), "r"(a[2]), "r"(a[3]), "r"(b[0]), "r"(b[1]));
}

// ====================================================== 1) gating from x
// Full fp32 gate straight from x (coalesced over v). One thread = one token.
__global__ void k_gate(const float* __restrict__ x, const float* __restrict__ Wg) {
    __shared__ float sW[E_ * L_];
    int tid = threadIdx.x, lane = tid & 31;
    for (int i = tid; i < E_ * L_; i += blockDim.x) sW[i] = Wg[i];
    __syncthreads();

    int b = blockIdx.y;
    int v = blockIdx.x * 256 + tid;
    int token = b * V_ + v;
    const float* xb = x + (size_t)b * L_ * V_ + v;

    float acc[E_];
#pragma unroll
    for (int e = 0; e < E_; e++) acc[e] = 0.f;
#pragma unroll 4
    for (int l = 0; l < L_; l++) {
        float xv = xb[(size_t)l * V_];
#pragma unroll
        for (int e = 0; e < E_; e++) acc[e] += xv * sW[e * L_ + l];
    }

    float mx = acc[0];
#pragma unroll
    for (int e = 1; e < E_; e++) mx = fmaxf(mx, acc[e]);
    float p[E_], s = 0.f;
#pragma unroll
    for (int e = 0; e < E_; e++) { p[e] = expf(acc[e] - mx); s += p[e]; }
    float inv = 1.f / s;
#pragma unroll
    for (int e = 0; e < E_; e++) {
        p[e] *= inv;
        g_prob[(size_t)token * E_ + e] = p[e];
    }
    // top-2, first index wins on ties (matches jax.lax.top_k)
    int e0 = 0;
#pragma unroll
    for (int e = 1; e < E_; e++) if (p[e] > p[e0]) e0 = e;
    int e1 = (e0 == 0) ? 1 : 0;
#pragma unroll
    for (int e = 0; e < E_; e++)
        if (e != e0 && p[e] > p[e1]) e1 = e;

    // warp-aggregated list append into (slot, expert) lists; list order is
    // irrelevant (each token writes a disjoint row of its slot buffer)
#pragma unroll
    for (int sel = 0; sel < 2; sel++) {
        int eS = sel ? e1 : e0;
        float wS = sel ? p[e1] : p[e0];
        for (int ei = 0; ei < E_; ei++) {
            unsigned m = __ballot_sync(0xFFFFFFFFu, eS == ei);
            if (eS == ei) {
                int li = sel * 8 + ei;
                int leader = __ffs(m) - 1;
                int base = 0;
                if (lane == leader) base = atomicAdd(&g_cnt[li], __popc(m));
                base = __shfl_sync(m, base, leader);
                int pos = base + __popc(m & ((1u << lane) - 1u));
                g_list [li * NTOK + pos] = token;
                g_wlist[li * NTOK + pos] = wS;
            }
        }
    }
}

// ====================================================== 2) input transpose
// Xt[b*V+v][l] = tf32_round(x[b][l][v])
__global__ void k_transpose_in(const float* __restrict__ x) {
    __shared__ float tile[32][33];
    int b = blockIdx.z, l0 = blockIdx.x * 32, v0 = blockIdx.y * 32;
    const float* xb = x + (size_t)b * L_ * V_;
#pragma unroll
    for (int k = 0; k < 32; k += 8) {
        int l = l0 + threadIdx.y + k;
        if (l < L_) tile[threadIdx.y + k][threadIdx.x] = xb[(size_t)l * V_ + v0 + threadIdx.x];
    }
    __syncthreads();
    float* Xb = g_Xt + (size_t)b * V_ * L_;
#pragma unroll
    for (int k = 0; k < 32; k += 8) {
        int v = v0 + threadIdx.y + k;
        int l = l0 + threadIdx.x;
        if (l < L_) Xb[(size_t)v * L_ + l] = f2tf(tile[threadIdx.x][threadIdx.y + k]);
    }
}

// ====================================================== 3) round We -> g_Wr
__global__ void k_round_we(const float* __restrict__ We) {
    int i = blockIdx.x * 256 + threadIdx.x;               // float4 index
    constexpr int N4 = E_ * P_ * L_ / 4;
    if (i >= N4) return;
    float4 v = ((const float4*)We)[i];
    v.x = f2tf(v.x); v.y = f2tf(v.y); v.z = f2tf(v.z); v.w = f2tf(v.w);
    ((float4*)g_Wr)[i] = v;
}

// ============================================= 4) grouped tf32 mma GEMM
// One block = one ((slot,expert) m-block, n-tile). 256 thr = 8 warps (2x4),
// warp tile 64x32, m16n8k8 tf32, BK=32 stages, 3-deep cp.async pipeline;
// prefetch for stage c+2 issues immediately after the barrier (before
// compute) to keep a full 2-step prefetch distance.
// Epilogue: STG.64 into slot-private buffer (race-free).
__global__ void __launch_bounds__(256, 2)
k_gemm(const float* __restrict__ be) {
    extern __shared__ char smem[];
    uint32_t sb = smem_u32(smem);
    int tid = threadIdx.x, warp = tid >> 5, lane = tid & 31;
    int ny = blockIdx.y, bx = blockIdx.x;

    // map block -> (list, m-block) by scanning the 16 list counts
    int li = -1, mblk = 0, cum = 0;
#pragma unroll
    for (int i = 0; i < 16; i++) {
        int c  = g_cnt[i];
        int nb = (c + MT - 1) / MT;
        if (li < 0 && bx < cum + nb) { li = i; mblk = bx - cum; }
        cum += nb;
    }
    if (li < 0) return;
    int slot = li >> 3, e = li & 7;
    int cnt  = g_cnt[li];
    int m0   = mblk * MT;
    int rows = min(MT, cnt - m0);

    int*   sTok = (int*)(smem + SM_TOK);
    float* sWt  = (float*)(smem + SM_W);
    if (tid < MT) {
        int gi = li * NTOK + m0 + tid;
        if (tid < rows) { sTok[tid] = g_list[gi]; sWt[tid] = g_wlist[gi]; }
        else            { sTok[tid] = 0;          sWt[tid] = 0.f; }
    }
    __syncthreads();

    const float* Bsrc = g_Wr + (size_t)e * P_ * L_;
    int n0 = ny * NTILE;

    // stage loader: A 1024 chunks + B 1024 chunks of 16B; 8 per thread.
    // Mapping q>>3 / q&7: 8 consecutive lanes cover one 128B row run.
    auto load_stage = [&](int c, int buf) {
        uint32_t base = sb + SM_ST + buf * STAGE_BYTES;
        int k0 = c * BK;
#pragma unroll
        for (int i = 0; i < 4; i++) {
            int q = i * 256 + tid;            // [0,1024)
            int row = q >> 3, j = q & 7;
            int kk = k0 + j * 4;
            int vb = (kk + 4 <= L_) ? 16 : 0;  // zfill K tail (exact zeros)
            const float* src = g_Xt + (size_t)sTok[row] * L_ + kk;
            cp16(base + (row * SA + j * 4) * 4, src, vb);
        }
        uint32_t bBase = base + MT * SA * 4;
#pragma unroll
        for (int i = 0; i < 4; i++) {
            int q = i * 256 + tid;
            int row = q >> 3, j = q & 7;
            int p = n0 + row;
            int kk = k0 + j * 4;
            int vb = (p < P_ && kk + 4 <= L_) ? 16 : 0;
            const float* src = Bsrc + (size_t)(p < P_ ? p : 0) * L_ + kk;
            cp16(bBase + (row * SA + j * 4) * 4, src, vb);
        }
        cp_commit();
    };

    int wm = warp & 1, wn = warp >> 1;          // 2 x 4 warp grid
    float acc[4][4][4];
#pragma unroll
    for (int a = 0; a < 4; a++)
#pragma unroll
        for (int b = 0; b < 4; b++)
#pragma unroll
            for (int d = 0; d < 4; d++) acc[a][b][d] = 0.f;

    int gid = lane >> 2, tig = lane & 3;        // fragment lane coords

    load_stage(0, 0);
    load_stage(1, 1);

    for (int c = 0; c < KSTEPS; c++) {
        cp_wait<1>();                 // stage c resident (c+1 may be in flight)
        __syncthreads();              // all warps past compute(c-1)
        // prefetch stage c+2 FIRST: its buffer was consumed at compute(c-1)
        // and the barrier above guarantees every warp is past that.
        if (c + 2 < KSTEPS)
            load_stage(c + 2, (c + 2) % NSTAGE);
        else
            cp_commit();   // keep group count uniform for cp_wait
        int buf = c % NSTAGE;
        const uint32_t* sA = (const uint32_t*)(smem + SM_ST + buf * STAGE_BYTES);
        const uint32_t* sB = sA + MT * SA;

#pragma unroll
        for (int ks = 0; ks < 4; ks++) {
            int kb = ks * 8;
            uint32_t af[4][4];
            uint32_t bf[4][2];
#pragma unroll
            for (int mf = 0; mf < 4; mf++) {
                int r0 = wm * 64 + mf * 16 + gid;
                af[mf][0] = sA[r0 * SA + kb + tig];
                af[mf][1] = sA[(r0 + 8) * SA + kb + tig];
                af[mf][2] = sA[r0 * SA + kb + tig + 4];
                af[mf][3] = sA[(r0 + 8) * SA + kb + tig + 4];
            }
#pragma unroll
            for (int nf = 0; nf < 4; nf++) {
                int n = wn * 32 + nf * 8 + gid;
                bf[nf][0] = sB[n * SA + kb + tig];
                bf[nf][1] = sB[n * SA + kb + tig + 4];
            }
#pragma unroll
            for (int nf = 0; nf < 4; nf++)
#pragma unroll
                for (int mf = 0; mf < 4; mf++)
                    mma_tf32(acc[mf][nf], af[mf], bf[nf]);
        }
    }

    // -------- epilogue: (acc + bias) * gate_weight, STG.64 into slot buffer
    float* Ybuf = slot ? g_Ys1 : g_Ys0;
    const float* beE = be + (size_t)e * P_;
#pragma unroll
    for (int mf = 0; mf < 4; mf++) {
        int r0 = wm * 64 + mf * 16 + gid;
#pragma unroll
        for (int half = 0; half < 2; half++) {
            int r = r0 + half * 8;
            if (r >= rows) continue;
            float w = sWt[r];
            float* dst = Ybuf + (size_t)sTok[r] * P_;
#pragma unroll
            for (int nf = 0; nf < 4; nf++) {
                int col = n0 + wn * 32 + nf * 8 + tig * 2;
                if (col >= P_) continue;
                float2 v;
                v.x = (acc[mf][nf][half * 2 + 0] + beE[col])     * w;
                v.y = (acc[mf][nf][half * 2 + 1] + beE[col + 1]) * w;
                *(float2*)(dst + col) = v;
            }
        }
    }
}

// ====================================================== 5) combine+transpose
// out[b][p][v] = Ys0[b*V+v][p] + Ys1[b*V+v][p]
__global__ void k_transpose_out(float* __restrict__ out) {
    __shared__ float tile[32][33];
    int b = blockIdx.z, p0 = blockIdx.x * 32, v0 = blockIdx.y * 32;
    const float* Y0 = g_Ys0 + (size_t)b * V_ * P_;
    const float* Y1 = g_Ys1 + (size_t)b * V_ * P_;
#pragma unroll
    for (int k = 0; k < 32; k += 8) {
        int v = v0 + threadIdx.y + k;
        int p = p0 + threadIdx.x;
        if (p < P_) {
            size_t idx = (size_t)v * P_ + p;
            tile[threadIdx.y + k][threadIdx.x] = Y0[idx] + Y1[idx];
        }
    }
    __syncthreads();
    float* ob = out + (size_t)b * P_ * V_;
#pragma unroll
    for (int k = 0; k < 32; k += 8) {
        int p = p0 + threadIdx.y + k;
        if (p < P_) ob[(size_t)p * V_ + v0 + threadIdx.x] = tile[threadIdx.x][threadIdx.y + k];
    }
}

// ====================================================== 6) gate mean tail
__global__ void k_gatemean(float* __restrict__ out) {
    int i = blockIdx.x * 256 + threadIdx.x;
    if (i >= V_ * E_) return;
    int v = i >> 3, e = i & 7;
    float s = 0.f;
    for (int b = 0; b < B_; b++) s += g_prob[(size_t)(b * V_ + v) * E_ + e];
    out[OUT_MAIN + i] = s * (1.f / B_);
}

// ============================================================== launch
extern "C" void kernel_launch(void* const* d_in, const int* in_sizes, int n_in,
                              void* d_out, int out_size) {
    const float* x  = (const float*)d_in[0];
    const float* Wg = (const float*)d_in[1];
    const float* We = (const float*)d_in[2];
    const float* be = (const float*)d_in[3];
    float* out = (float*)d_out;
    (void)in_sizes; (void)n_in;

    cudaFuncSetAttribute(k_gemm, cudaFuncAttributeMaxDynamicSharedMemorySize, SM_TOTAL);

    void* pCnt = nullptr;
    cudaGetSymbolAddress(&pCnt, g_cnt);
    cudaMemsetAsync(pCnt, 0, 16 * sizeof(int));

    k_gate<<<dim3(V_ / 256, B_), 256>>>(x, Wg);
    dim3 tb(32, 8);
    k_transpose_in<<<dim3(23, 32, 32), tb>>>(x);
    k_round_we<<<(E_ * P_ * L_ / 4 + 255) / 256, 256>>>(We);

    // per slot: <=256 full m-blocks + <=8 partials -> 264; two slots -> 528
    int maxblk = 2 * (NTOK / MT + 8);                     // 528
    k_gemm<<<dim3(maxblk, NNT), 256, SM_TOTAL>>>(be);

    k_transpose_out<<<dim3(23, 32, 32), tb>>>(out);
    if (out_size > OUT_MAIN)
        k_gatemean<<<(V_ * E_ + 255) / 256, 256>>>(out);
}

// round 17
// speedup vs baseline: 1.0750x; 1.0750x over previous
#include <cuda_runtime.h>
#include <cstdint>

#define DI static __device__ __forceinline__

// ---------------------------------------------------------------- constants
constexpr int B_ = 32, L_ = 720, V_ = 1024, P_ = 720, E_ = 8;
constexpr int NTOK = B_ * V_;                 // 32768 tokens
constexpr int OUT_MAIN = B_ * P_ * V_;        // 23592960
constexpr int MT = 128;                       // block M (tokens)
constexpr int NTILE = 128;                    // block N (output cols)
constexpr int NNT = 6;                        // ceil(720/128)
constexpr int BK = 32;                        // K per stage
constexpr int KSTEPS = 23;                    // 22 full + 1 half (zfill)
constexpr int NSTAGE = 3;

// smem geometry for the GEMM kernel
constexpr int SA = 36;                        // padded row stride (floats)
constexpr int STAGE_FLOATS = (MT + NTILE) * SA;      // 9216 floats
constexpr int STAGE_BYTES = STAGE_FLOATS * 4;        // 36864
constexpr int SM_TOK = 0;                     // 128 ints
constexpr int SM_W   = 512;                   // 128 floats
constexpr int SM_ST  = 1024;                  // stage buffers
constexpr int SM_TOTAL = SM_ST + NSTAGE * STAGE_BYTES;   // 111616

// ------------------------------------------------------- scratch (globals)
__device__ float g_Xt[(size_t)NTOK * L_];     // token-major input, tf32-rounded
__device__ float g_Wr[(size_t)E_ * P_ * L_];  // We tf32-rounded (16.6 MB)
__device__ float g_Ys0[(size_t)NTOK * P_];    // slot-0 contribution (94 MB)
__device__ float g_Ys1[(size_t)NTOK * P_];    // slot-1 contribution (94 MB)
__device__ float g_prob[(size_t)NTOK * E_];   // softmax probs
__device__ int   g_cnt[16];                   // per (slot,expert) counts
__device__ int   g_list [16 * NTOK];          // gathered token ids
__device__ float g_wlist[16 * NTOK];          // gate weights

// ------------------------------------------------------------- PTX helpers
DI uint32_t smem_u32(const void* p) {
    uint32_t a;
    asm("{ .reg .u64 t; cvta.to.shared.u64 t, %1; cvt.u32.u64 %0, t; }"
        : "=r"(a) : "l"(p));
    return a;
}

DI void cp16(uint32_t dst, const void* src, int srcbytes) {
    asm volatile("cp.async.cg.shared.global [%0], [%1], 16, %2;"
                 :: "r"(dst), "l"(src), "r"(srcbytes));
}
DI void cp_commit() { asm volatile("cp.async.commit_group;" ::: "memory"); }
template <int N>
DI void cp_wait() { asm volatile("cp.async.wait_group %0;" :: "n"(N) : "memory"); }

DI float f2tf(float f) {
    uint32_t r;
    asm("cvt.rna.tf32.f32 %0, %1;" : "=r"(r) : "f"(f));
    return __uint_as_float(r);
}

DI void mma_tf32(float* d, const uint32_t* a, const uint32_t* b) {
    asm volatile(
        "mma.sync.aligned.m16n8k8.row.col.f32.tf32.tf32.f32 "
        "{%0,%1,%2,%3}, {%4,%5,%6,%7}, {%8,%9}, {%0,%1,%2,%3};"
        : "+f"(d[0]), "+f"(d[1]), "+f"(d[2]), "+f"(d[3])
        : "r"(a[0]), "r"(a[1]), "r"(a[2]), "r"(a[3]), "r"(b[0]), "r"(b[1]));
}

// ====================================================== 1) gating from x
// Full fp32 gate straight from x (coalesced over v). One thread = one token.
__global__ void k_gate(const float* __restrict__ x, const float* __restrict__ Wg) {
    __shared__ float sW[E_ * L_];
    int tid = threadIdx.x, lane = tid & 31;
    for (int i = tid; i < E_ * L_; i += blockDim.x) sW[i] = Wg[i];
    __syncthreads();

    int b = blockIdx.y;
    int v = blockIdx.x * 256 + tid;
    int token = b * V_ + v;
    const float* xb = x + (size_t)b * L_ * V_ + v;

    float acc[E_];
#pragma unroll
    for (int e = 0; e < E_; e++) acc[e] = 0.f;
#pragma unroll 4
    for (int l = 0; l < L_; l++) {
        float xv = xb[(size_t)l * V_];
#pragma unroll
        for (int e = 0; e < E_; e++) acc[e] += xv * sW[e * L_ + l];
    }

    float mx = acc[0];
#pragma unroll
    for (int e = 1; e < E_; e++) mx = fmaxf(mx, acc[e]);
    float p[E_], s = 0.f;
#pragma unroll
    for (int e = 0; e < E_; e++) { p[e] = expf(acc[e] - mx); s += p[e]; }
    float inv = 1.f / s;
#pragma unroll
    for (int e = 0; e < E_; e++) {
        p[e] *= inv;
        g_prob[(size_t)token * E_ + e] = p[e];
    }
    // top-2, first index wins on ties (matches jax.lax.top_k)
    int e0 = 0;
#pragma unroll
    for (int e = 1; e < E_; e++) if (p[e] > p[e0]) e0 = e;
    int e1 = (e0 == 0) ? 1 : 0;
#pragma unroll
    for (int e = 0; e < E_; e++)
        if (e != e0 && p[e] > p[e1]) e1 = e;

    // warp-aggregated list append into (slot, expert) lists; list order is
    // irrelevant (each token writes a disjoint row of its slot buffer)
#pragma unroll
    for (int sel = 0; sel < 2; sel++) {
        int eS = sel ? e1 : e0;
        float wS = sel ? p[e1] : p[e0];
        for (int ei = 0; ei < E_; ei++) {
            unsigned m = __ballot_sync(0xFFFFFFFFu, eS == ei);
            if (eS == ei) {
                int li = sel * 8 + ei;
                int leader = __ffs(m) - 1;
                int base = 0;
                if (lane == leader) base = atomicAdd(&g_cnt[li], __popc(m));
                base = __shfl_sync(m, base, leader);
                int pos = base + __popc(m & ((1u << lane) - 1u));
                g_list [li * NTOK + pos] = token;
                g_wlist[li * NTOK + pos] = wS;
            }
        }
    }
}

// ====================================================== 2) input transpose
// Xt[b*V+v][l] = tf32_round(x[b][l][v]); 64x64 tiles.
__global__ void k_transpose_in(const float* __restrict__ x) {
    __shared__ float tile[64][65];
    int b = blockIdx.z, l0 = blockIdx.x * 64, v0 = blockIdx.y * 64;
    int tx = threadIdx.x, ty = threadIdx.y;
    const float* xb = x + (size_t)b * L_ * V_;
#pragma unroll
    for (int ky = 0; ky < 64; ky += 8) {
        int l = l0 + ty + ky;
        if (l < L_) {
            const float* src = xb + (size_t)l * V_ + v0;
            tile[ty + ky][tx]      = src[tx];
            tile[ty + ky][tx + 32] = src[tx + 32];
        }
    }
    __syncthreads();
    float* Xb = g_Xt + (size_t)b * V_ * L_;
#pragma unroll
    for (int ky = 0; ky < 64; ky += 8) {
        int v = v0 + ty + ky;
        int l1 = l0 + tx, l2 = l0 + tx + 32;
        float* dst = Xb + (size_t)v * L_;
        if (l1 < L_) dst[l1] = f2tf(tile[tx][ty + ky]);
        if (l2 < L_) dst[l2] = f2tf(tile[tx + 32][ty + ky]);
    }
}

// ====================================================== 3) round We -> g_Wr
__global__ void k_round_we(const float* __restrict__ We) {
    int i = blockIdx.x * 256 + threadIdx.x;               // float4 index
    constexpr int N4 = E_ * P_ * L_ / 4;
    if (i >= N4) return;
    float4 v = ((const float4*)We)[i];
    v.x = f2tf(v.x); v.y = f2tf(v.y); v.z = f2tf(v.z); v.w = f2tf(v.w);
    ((float4*)g_Wr)[i] = v;
}

// ============================================= 4) grouped tf32 mma GEMM
// One block = one ((slot,expert) m-block, n-tile). 256 thr = 8 warps (2x4),
// warp tile 64x32, m16n8k8 tf32, BK=32 stages, 3-deep cp.async pipeline.
// Prefetch for stage c+2 is split: A-half issues after ks=0's mmas, B-half
// (plus commit) after ks=1's — loads start earlier without contending with
// the first fragment LDS of the step.
// Epilogue: STG.64 into slot-private buffer (race-free).
__global__ void __launch_bounds__(256, 2)
k_gemm(const float* __restrict__ be) {
    extern __shared__ char smem[];
    uint32_t sb = smem_u32(smem);
    int tid = threadIdx.x, warp = tid >> 5, lane = tid & 31;
    int ny = blockIdx.y, bx = blockIdx.x;

    // map block -> (list, m-block) by scanning the 16 list counts
    int li = -1, mblk = 0, cum = 0;
#pragma unroll
    for (int i = 0; i < 16; i++) {
        int c  = g_cnt[i];
        int nb = (c + MT - 1) / MT;
        if (li < 0 && bx < cum + nb) { li = i; mblk = bx - cum; }
        cum += nb;
    }
    if (li < 0) return;
    int slot = li >> 3, e = li & 7;
    int cnt  = g_cnt[li];
    int m0   = mblk * MT;
    int rows = min(MT, cnt - m0);

    int*   sTok = (int*)(smem + SM_TOK);
    float* sWt  = (float*)(smem + SM_W);
    if (tid < MT) {
        int gi = li * NTOK + m0 + tid;
        if (tid < rows) { sTok[tid] = g_list[gi]; sWt[tid] = g_wlist[gi]; }
        else            { sTok[tid] = 0;          sWt[tid] = 0.f; }
    }
    __syncthreads();

    const float* Bsrc = g_Wr + (size_t)e * P_ * L_;
    int n0 = ny * NTILE;

    // stage loaders (A half / B half; B half commits the group).
    // Mapping q>>3 / q&7: 8 consecutive lanes cover one 128B row run.
    auto load_A = [&](int c, int buf) {
        uint32_t base = sb + SM_ST + buf * STAGE_BYTES;
        int k0 = c * BK;
#pragma unroll
        for (int i = 0; i < 4; i++) {
            int q = i * 256 + tid;            // [0,1024)
            int row = q >> 3, j = q & 7;
            int kk = k0 + j * 4;
            int vb = (kk + 4 <= L_) ? 16 : 0;  // zfill K tail (exact zeros)
            const float* src = g_Xt + (size_t)sTok[row] * L_ + kk;
            cp16(base + (row * SA + j * 4) * 4, src, vb);
        }
    };
    auto load_B = [&](int c, int buf) {
        uint32_t bBase = sb + SM_ST + buf * STAGE_BYTES + MT * SA * 4;
        int k0 = c * BK;
#pragma unroll
        for (int i = 0; i < 4; i++) {
            int q = i * 256 + tid;
            int row = q >> 3, j = q & 7;
            int p = n0 + row;
            int kk = k0 + j * 4;
            int vb = (p < P_ && kk + 4 <= L_) ? 16 : 0;
            const float* src = Bsrc + (size_t)(p < P_ ? p : 0) * L_ + kk;
            cp16(bBase + (row * SA + j * 4) * 4, src, vb);
        }
        cp_commit();
    };

    int wm = warp & 1, wn = warp >> 1;          // 2 x 4 warp grid
    float acc[4][4][4];
#pragma unroll
    for (int a = 0; a < 4; a++)
#pragma unroll
        for (int b = 0; b < 4; b++)
#pragma unroll
            for (int d = 0; d < 4; d++) acc[a][b][d] = 0.f;

    int gid = lane >> 2, tig = lane & 3;        // fragment lane coords

    load_A(0, 0); load_B(0, 0);
    load_A(1, 1); load_B(1, 1);

    for (int c = 0; c < KSTEPS; c++) {
        cp_wait<1>();                 // stage c resident (c+1 may be in flight)
        __syncthreads();              // all warps past compute(c-1)
        int buf = c % NSTAGE;
        const uint32_t* sA = (const uint32_t*)(smem + SM_ST + buf * STAGE_BYTES);
        const uint32_t* sB = sA + MT * SA;
        bool pf = (c + 2 < KSTEPS);
        int pbuf = (c + 2) % NSTAGE;   // consumed at compute(c-1): safe to fill

#pragma unroll
        for (int ks = 0; ks < 4; ks++) {
            int kb = ks * 8;
            uint32_t af[4][4];
            uint32_t bf[4][2];
#pragma unroll
            for (int mf = 0; mf < 4; mf++) {
                int r0 = wm * 64 + mf * 16 + gid;
                af[mf][0] = sA[r0 * SA + kb + tig];
                af[mf][1] = sA[(r0 + 8) * SA + kb + tig];
                af[mf][2] = sA[r0 * SA + kb + tig + 4];
                af[mf][3] = sA[(r0 + 8) * SA + kb + tig + 4];
            }
#pragma unroll
            for (int nf = 0; nf < 4; nf++) {
                int n = wn * 32 + nf * 8 + gid;
                bf[nf][0] = sB[n * SA + kb + tig];
                bf[nf][1] = sB[n * SA + kb + tig + 4];
            }
#pragma unroll
            for (int nf = 0; nf < 4; nf++)
#pragma unroll
                for (int mf = 0; mf < 4; mf++)
                    mma_tf32(acc[mf][nf], af[mf], bf[nf]);

            if (ks == 0 && pf) load_A(c + 2, pbuf);
            if (ks == 1) {
                if (pf) load_B(c + 2, pbuf);
                else    cp_commit();   // keep group count uniform for cp_wait
            }
        }
    }

    // -------- epilogue: (acc + bias) * gate_weight, STG.64 into slot buffer
    float* Ybuf = slot ? g_Ys1 : g_Ys0;
    const float* beE = be + (size_t)e * P_;
#pragma unroll
    for (int mf = 0; mf < 4; mf++) {
        int r0 = wm * 64 + mf * 16 + gid;
#pragma unroll
        for (int half = 0; half < 2; half++) {
            int r = r0 + half * 8;
            if (r >= rows) continue;
            float w = sWt[r];
            float* dst = Ybuf + (size_t)sTok[r] * P_;
#pragma unroll
            for (int nf = 0; nf < 4; nf++) {
                int col = n0 + wn * 32 + nf * 8 + tig * 2;
                if (col >= P_) continue;
                float2 v;
                v.x = (acc[mf][nf][half * 2 + 0] + beE[col])     * w;
                v.y = (acc[mf][nf][half * 2 + 1] + beE[col + 1]) * w;
                *(float2*)(dst + col) = v;
            }
        }
    }
}

// ====================================================== 5) combine+transpose
// out[b][p][v] = Ys0[b*V+v][p] + Ys1[b*V+v][p]; 64x64 tiles.
__global__ void k_transpose_out(float* __restrict__ out) {
    __shared__ float tile[64][65];
    int b = blockIdx.z, p0 = blockIdx.x * 64, v0 = blockIdx.y * 64;
    int tx = threadIdx.x, ty = threadIdx.y;
    const float* Y0 = g_Ys0 + (size_t)b * V_ * P_;
    const float* Y1 = g_Ys1 + (size_t)b * V_ * P_;
#pragma unroll
    for (int ky = 0; ky < 64; ky += 8) {
        int v = v0 + ty + ky;
        size_t rb = (size_t)v * P_;
        int p1 = p0 + tx, p2 = p0 + tx + 32;
        if (p1 < P_) tile[ty + ky][tx]      = Y0[rb + p1] + Y1[rb + p1];
        if (p2 < P_) tile[ty + ky][tx + 32] = Y0[rb + p2] + Y1[rb + p2];
    }
    __syncthreads();
    float* ob = out + (size_t)b * P_ * V_;
#pragma unroll
    for (int ky = 0; ky < 64; ky += 8) {
        int p = p0 + ty + ky;
        if (p < P_) {
            float* dst = ob + (size_t)p * V_ + v0;
            dst[tx]      = tile[tx][ty + ky];
            dst[tx + 32] = tile[tx + 32][ty + ky];
        }
    }
}

// ====================================================== 6) gate mean tail
__global__ void k_gatemean(float* __restrict__ out) {
    int i = blockIdx.x * 256 + threadIdx.x;
    if (i >= V_ * E_) return;
    int v = i >> 3, e = i & 7;
    float s = 0.f;
    for (int b = 0; b < B_; b++) s += g_prob[(size_t)(b * V_ + v) * E_ + e];
    out[OUT_MAIN + i] = s * (1.f / B_);
}

// ============================================================== launch
extern "C" void kernel_launch(void* const* d_in, const int* in_sizes, int n_in,
                              void* d_out, int out_size) {
    const float* x  = (const float*)d_in[0];
    const float* Wg = (const float*)d_in[1];
    const float* We = (const float*)d_in[2];
    const float* be = (const float*)d_in[3];
    float* out = (float*)d_out;
    (void)in_sizes; (void)n_in;

    cudaFuncSetAttribute(k_gemm, cudaFuncAttributeMaxDynamicSharedMemorySize, SM_TOTAL);

    void* pCnt = nullptr;
    cudaGetSymbolAddress(&pCnt, g_cnt);
    cudaMemsetAsync(pCnt, 0, 16 * sizeof(int));

    k_gate<<<dim3(V_ / 256, B_), 256>>>(x, Wg);
    dim3 tb(32, 8);
    k_transpose_in<<<dim3(12, 16, 32), tb>>>(x);    // 64x64 tiles over (L,V)
    k_round_we<<<(E_ * P_ * L_ / 4 + 255) / 256, 256>>>(We);

    // per slot: <=256 full m-blocks + <=8 partials -> 264; two slots -> 528
    int maxblk = 2 * (NTOK / MT + 8);                     // 528
    k_gemm<<<dim3(maxblk, NNT), 256, SM_TOTAL>>>(be);

    k_transpose_out<<<dim3(12, 16, 32), tb>>>(out); // 64x64 tiles over (P,V)
    if (out_size > OUT_MAIN)
        k_gatemean<<<(V_ * E_ + 255) / 256, 256>>>(out);
}